// round 12
// baseline (speedup 1.0000x reference)
#include <cuda_runtime.h>
#include <math.h>
#include <stdint.h>

#define NPRED_TOTAL 259584      // 32 * 8112
#define NP0         8112        // predictions in batch 0 (3*52*52)
#define HW_         2704        // 52*52
#define ATTRS       85
#define OUT_ELEMS   22064640    // 32*8112*85
#define MAXDET      100
#define NCLS        80
#define CLS_CAP     1024
#define MTX_CAP     256
#define MTX_W       8
#define KEPT_MAX    8192
#define NBUCK       8192        // (key>>31)&0x1FFF : exp-LSB + 12 mantissa bits
#define POOL_CAP    1536
#define TOT_BLOCKS  (NPRED_TOTAL / 64)

// ---- device scratch ----
__device__ float4   g_obox[NP0];
__device__ float4   g_corners[NP0];
__device__ float    g_conf[NP0];
__device__ float    g_clsconf[NP0];
__device__ float    g_clspred[NP0];
__device__ uint64_t g_cls_list[NCLS * CLS_CAP];
__device__ int      g_cls_cnt[NCLS];
__device__ uint64_t g_kept[KEPT_MAX];
__device__ int      g_kcount;
__device__ int      g_done;

// key (52 bits) = score_inv(32) << 20 | idx(13) << 7 | cls(7)

__device__ __forceinline__ float sigf(float x) { return 1.0f / (1.0f + expf(-x)); }

// ---------------------------------------------------------------------------
// Extract: batch-0 candidates straight from raw input (1 thread per pred).
// Arithmetic expressions identical to decode's -> bitwise-same values.
// ---------------------------------------------------------------------------
__global__ __launch_bounds__(256) void extract_kernel(
    const float* __restrict__ in,
    const float* __restrict__ anchors)
{
    const int n = blockIdx.x * 256 + threadIdx.x;
    if (n >= NP0) return;
    const int a  = n / HW_;
    const int hw = n - a * HW_;
    const int gy = hw / 52;
    const int gx = hw - gy * 52;

    const float* p = in + (long)(a * 85) * HW_ + hw;   // batch 0

    float conf = sigf(p[(long)4 * HW_]);
    float cc = sigf(p[(long)5 * HW_]); int cp = 0;
    #pragma unroll 16
    for (int c = 1; c < NCLS; c++) {
        float v = sigf(p[(long)(5 + c) * HW_]);
        if (v > cc) { cc = v; cp = c; }      // strict > : lowest idx on ties
    }
    float score = conf * cc;
    if (score < 0.5f) return;

    float aw = anchors[(6 + a) * 2 + 0] * 0.125f;
    float ah = anchors[(6 + a) * 2 + 1] * 0.125f;
    float bx = (sigf(p[0]) + (float)gx) / 52.0f;
    float by = (sigf(p[(long)1 * HW_]) + (float)gy) / 52.0f;
    float bw = (expf(p[(long)2 * HW_]) * aw) / 52.0f;
    float bh = (expf(p[(long)3 * HW_]) * ah) / 52.0f;

    float hx = bw * 0.5f, hy = bh * 0.5f;
    float x1 = bx - hx, y1 = by - hy, x2 = bx + hx, y2 = by + hy;
    float off = (float)cp * 4096.0f;
    g_corners[n] = make_float4(x1, y1, x2, y2);
    g_obox[n]    = make_float4(x1 + off, y1 + off, x2 + off, y2 + off);
    g_conf[n]    = conf;
    g_clsconf[n] = cc;
    g_clspred[n] = (float)cp;
    uint64_t key = ((uint64_t)(__float_as_uint(score) ^ 0xFFFFFFFFu) << 20)
                 | ((uint64_t)(unsigned)n << 7) | (unsigned)cp;
    int pos = atomicAdd(&g_cls_cnt[cp], 1);
    if (pos < CLS_CAP) g_cls_list[cp * CLS_CAP + pos] = key;
}

// ---------------------------------------------------------------------------
// Decode: pure layout transform now (extraction removed). 64 preds/block.
// ---------------------------------------------------------------------------
__global__ __launch_bounds__(256) void decode_kernel(
    const float* __restrict__ in,
    const float* __restrict__ anchors,
    float* __restrict__ out)
{
    __shared__ float sm[64 * ATTRS];
    const int tx = threadIdx.x;
    const int q  = tx >> 6;
    const int lp = tx & 63;
    const int n  = blockIdx.x * 64 + lp;
    const int b  = n / NP0;
    const int r  = n - b * NP0;
    const int a  = r / HW_;
    const int hw = r - a * HW_;
    const int gy = hw / 52;
    const int gx = hw - gy * 52;

    const float* p = in + ((long)(b * 255 + a * 85)) * HW_ + hw;
    float* row = sm + lp * ATTRS;

    float t[22];
    #pragma unroll
    for (int k = 0; k < 22; k++) {
        int e = q + 4 * k;
        if (e < ATTRS) t[k] = __ldcs(p + (long)e * HW_);
    }

    if (q == 0) {
        row[0] = (sigf(t[0]) + (float)gx) / 52.0f;
        row[4] = sigf(t[1]);
        #pragma unroll
        for (int k = 2; k < 22; k++) row[4 * k] = sigf(t[k]);
    } else if (q == 1) {
        row[1] = (sigf(t[0]) + (float)gy) / 52.0f;
        #pragma unroll
        for (int k = 1; k < 21; k++) row[1 + 4 * k] = sigf(t[k]);
    } else if (q == 2) {
        float aw = anchors[(6 + a) * 2 + 0] * 0.125f;
        row[2] = (expf(t[0]) * aw) / 52.0f;
        #pragma unroll
        for (int k = 1; k < 21; k++) row[2 + 4 * k] = sigf(t[k]);
    } else {
        float ah = anchors[(6 + a) * 2 + 1] * 0.125f;
        row[3] = (expf(t[0]) * ah) / 52.0f;
        #pragma unroll
        for (int k = 1; k < 21; k++) row[3 + 4 * k] = sigf(t[k]);
    }
    __syncthreads();

    const float4* sm4 = (const float4*)sm;
    float4* ob4 = (float4*)(out + (long)blockIdx.x * (64 * ATTRS));
    #pragma unroll 6
    for (int i = tx; i < (64 * ATTRS) / 4; i += 256) __stcs(ob4 + i, sm4[i]);
}

// ---------------------------------------------------------------------------
// Fused NMS (R11 logic; fences reduced to single-thread release/acquire)
// ---------------------------------------------------------------------------
__global__ __launch_bounds__(256) void nms_kernel(float* __restrict__ out)
{
    __shared__ __align__(16) char buf[45056];
    uint64_t* s_key  = (uint64_t*)buf;
    uint64_t* s_sort = (uint64_t*)(buf + 8192);
    float4*   s_box  = (float4*)(buf + 16384);
    unsigned* s_thr  = (unsigned*)(buf + 32768);
    int*      s_hist = (int*)buf;
    uint64_t* s_pool = (uint64_t*)(buf + 32768);

    __shared__ int s_kidx[MAXDET];
    __shared__ int s_ord[MAXDET];
    __shared__ int s_nk, s_gbase, s_ticket, s_bstar, s_pcnt;

    const int tid = threadIdx.x;
    const int c   = blockIdx.x;
    int nc = g_cls_cnt[c]; if (nc > CLS_CAP) nc = CLS_CAP;

    for (int i = tid; i < nc; i += 256) s_key[i] = g_cls_list[c * CLS_CAP + i];
    __syncthreads();

    for (int i = tid; i < nc; i += 256) {
        uint64_t my = s_key[i];
        int rk = 0;
        for (int j = 0; j < nc; j++) rk += (s_key[j] < my) ? 1 : 0;
        s_sort[rk] = my;
    }
    __syncthreads();

    for (int i = tid; i < nc; i += 256) {
        int orig = (int)((s_sort[i] >> 7) & 0x1FFFu);
        s_box[i] = g_obox[orig];
    }
    __syncthreads();

    if (nc <= MTX_CAP) {
        if (tid < nc) {
            unsigned w[MTX_W];
            #pragma unroll
            for (int k = 0; k < MTX_W; k++) w[k] = 0u;
            float4 Q = s_box[tid];
            float aI = (Q.z - Q.x) * (Q.w - Q.y);
            for (int j = 0; j < tid; j++) {
                float4 P = s_box[j];
                float aJ = (P.z - P.x) * (P.w - P.y);
                float ltx = fmaxf(P.x, Q.x), lty = fmaxf(P.y, Q.y);
                float rbx = fminf(P.z, Q.z), rby = fminf(P.w, Q.w);
                float iw = fmaxf(rbx - ltx, 0.0f), ih = fmaxf(rby - lty, 0.0f);
                float inter = iw * ih;
                float den = aJ + aI - inter + 1e-9f;
                if (inter / den > 0.4f) w[j >> 5] |= 1u << (j & 31);
            }
            #pragma unroll
            for (int k = 0; k < MTX_W; k++) s_thr[tid * MTX_W + k] = w[k];
        }
        __syncthreads();

        if (tid < 32) {
            unsigned kw = 0u;
            int nk = 0;
            for (int i = 0; i < nc && nk < MAXDET; i++) {
                unsigned tw = (tid < MTX_W) ? (s_thr[i * MTX_W + tid] & kw) : 0u;
                if (__ballot_sync(0xffffffffu, tw != 0u) == 0u) {
                    if (tid == 0) s_kidx[nk] = i;
                    if (tid == (i >> 5)) kw |= 1u << (i & 31);
                    nk++;
                }
            }
            if (tid == 0) s_nk = nk;
        }
    } else {
        if (tid < 32) {
            const int lane = tid;
            int nk = 0;
            for (int i = 0; i < nc && nk < MAXDET; i++) {
                float4 B = s_box[i];
                float aC = (B.z - B.x) * (B.w - B.y);
                bool sup = false;
                #pragma unroll
                for (int t = 0; t < 4; t++) {
                    int idx = lane + (t << 5);
                    if (idx < nk) {
                        float4 K = s_box[s_kidx[idx]];
                        float aK = (K.z - K.x) * (K.w - K.y);
                        float ltx = fmaxf(K.x, B.x), lty = fmaxf(K.y, B.y);
                        float rbx = fminf(K.z, B.z), rby = fminf(K.w, B.w);
                        float iw = fmaxf(rbx - ltx, 0.0f), ih = fmaxf(rby - lty, 0.0f);
                        float inter = iw * ih;
                        float den = aK + aC - inter + 1e-9f;
                        if (inter / den > 0.4f) sup = true;
                    }
                }
                if (__ballot_sync(0xffffffffu, sup) == 0u) {
                    if (lane == 0) s_kidx[nk] = i;
                    nk++;
                    __syncwarp();
                }
            }
            if (lane == 0) s_nk = nk;
        }
    }
    __syncthreads();

    const int nk = s_nk;
    if (tid == 0) s_gbase = (nk > 0) ? atomicAdd(&g_kcount, nk) : 0;
    __syncthreads();
    for (int t = tid; t < nk; t += 256) {
        int gp = s_gbase + t;
        if (gp < KEPT_MAX) g_kept[gp] = s_sort[s_kidx[t]];
    }
    if (tid == 0) g_cls_cnt[c] = 0;

    // release: writers' stores ordered by bar.sync, single-thread fence+ticket
    __syncthreads();
    if (tid == 0) {
        __threadfence();
        s_ticket = atomicAdd(&g_done, 1);
    }
    __syncthreads();
    if (s_ticket != NCLS - 1) return;

    // acquire: single-thread fence, distributed by bar.sync
    if (tid == 0) __threadfence();
    __syncthreads();

    // ===== last block: histogram top-100 merge (fine buckets) =====
    int K = g_kcount; if (K > KEPT_MAX) K = KEPT_MAX;
    const int np = (K < MAXDET) ? K : MAXDET;

    for (int i = tid; i < NBUCK; i += 256) s_hist[i] = 0;
    if (tid == 0) { s_pcnt = 0; s_bstar = -1; }
    __syncthreads();

    for (int i = tid; i < K; i += 256)
        atomicAdd(&s_hist[(int)((g_kept[i] >> 31) & 0x1FFFu)], 1);
    __syncthreads();

    if (tid < 32 && np > 0) {
        const int CH = NBUCK / 32;
        int sum = 0;
        for (int j = 0; j < CH; j++) sum += s_hist[tid * CH + j];
        int excl = sum;
        #pragma unroll
        for (int off = 1; off < 32; off <<= 1) {
            int v = __shfl_up_sync(0xffffffffu, excl, off);
            if ((int)tid >= off) excl += v;
        }
        excl -= sum;
        bool has = (excl < np) && (excl + sum >= np);
        unsigned bal = __ballot_sync(0xffffffffu, has);
        int src = __ffs(bal) - 1;
        if ((int)tid == src) {
            int run = excl;
            for (int j = 0; j < CH; j++) {
                run += s_hist[tid * CH + j];
                if (run >= np) { s_bstar = tid * CH + j; break; }
            }
        }
    }
    __syncthreads();

    const int bstar = s_bstar;
    for (int i = tid; i < K; i += 256) {
        uint64_t k = g_kept[i];
        if ((int)((k >> 31) & 0x1FFFu) <= bstar) {
            int p = atomicAdd(&s_pcnt, 1);
            if (p < POOL_CAP) s_pool[p] = k;
        }
    }
    __syncthreads();

    int P = s_pcnt; if (P > POOL_CAP) P = POOL_CAP;
    for (int i = tid; i < P; i += 256) {
        uint64_t my = s_pool[i];
        int rk = 0;
        for (int j = 0; j < P; j++) rk += (s_pool[j] < my) ? 1 : 0;
        if (rk < np) s_ord[rk] = (int)((my >> 7) & 0x1FFFu);
    }
    __syncthreads();

    if (tid < MAXDET) {
        float* d = out + (long)OUT_ELEMS + tid * 7;
        if (tid < np) {
            int orig = s_ord[tid];
            float4 c4 = g_corners[orig];
            d[0] = c4.y * 416.0f;
            d[1] = c4.x * 416.0f;
            d[2] = c4.w * 416.0f;
            d[3] = c4.z * 416.0f;
            d[4] = g_conf[orig];
            d[5] = g_clsconf[orig];
            d[6] = g_clspred[orig];
        } else {
            #pragma unroll
            for (int e = 0; e < 7; e++) d[e] = 0.0f;
        }
    }

    if (tid == 0) { g_kcount = 0; g_done = 0; }
}

// ---------------------------------------------------------------------------
// Launch: fork at t=0. Side stream: extract(b0 raw) -> nms. Main: full decode.
// ---------------------------------------------------------------------------
extern "C" void kernel_launch(void* const* d_in, const int* in_sizes, int n_in,
                              void* d_out, int out_size)
{
    const float* in      = (const float*)d_in[0];
    const float* anchors = (const float*)d_in[1];
    float* out = (float*)d_out;

    static cudaStream_t s2 = nullptr;
    static cudaEvent_t  e1 = nullptr, e2 = nullptr;
    if (!s2) {   // first call is the uncaptured correctness run
        cudaStreamCreateWithFlags(&s2, cudaStreamNonBlocking);
        cudaEventCreateWithFlags(&e1, cudaEventDisableTiming);
        cudaEventCreateWithFlags(&e2, cudaEventDisableTiming);
    }

    cudaEventRecord(e1, 0);
    cudaStreamWaitEvent(s2, e1, 0);

    extract_kernel<<<(NP0 + 255) / 256, 256, 0, s2>>>(in, anchors);
    nms_kernel<<<NCLS, 256, 0, s2>>>(out);

    decode_kernel<<<TOT_BLOCKS, 256>>>(in, anchors, out);

    cudaEventRecord(e2, s2);
    cudaStreamWaitEvent(0, e2, 0);
}

// round 13
// speedup vs baseline: 1.0349x; 1.0349x over previous
#include <cuda_runtime.h>
#include <math.h>
#include <stdint.h>

#define NPRED_TOTAL 259584      // 32 * 8112
#define NP0         8112        // predictions in batch 0 (3*52*52)
#define HW_         2704        // 52*52
#define ATTRS       85
#define OUT_ELEMS   22064640    // 32*8112*85
#define MAXDET      100
#define NCLS        80
#define CLS_CAP     1024
#define MTX_CAP     256
#define MTX_W       8
#define KEPT_MAX    8192
#define NBUCK       8192        // (key>>31)&0x1FFF : exp-LSB + 12 mantissa bits
#define POOL_CAP    1536
#define TOT_BLOCKS  (NPRED_TOTAL / 64)

// ---- device scratch ----
__device__ float4   g_obox[NP0];
__device__ float4   g_corners[NP0];
__device__ float    g_conf[NP0];
__device__ float    g_clsconf[NP0];
__device__ float    g_clspred[NP0];
__device__ uint64_t g_cls_list[NCLS * CLS_CAP];
__device__ int      g_cls_cnt[NCLS];
__device__ uint64_t g_kept[KEPT_MAX];
__device__ int      g_kcount;
__device__ int      g_done;

// key (52 bits) = score_inv(32) << 20 | idx(13) << 7 | cls(7)

__device__ __forceinline__ float sigf(float x) { return 1.0f / (1.0f + expf(-x)); }

// ---------------------------------------------------------------------------
// Extract v2: batch-0 candidates from raw input; 4 threads per prediction
// (20-class contiguous chunks each), shfl-combined argmax with exact
// lowest-index tie-breaking. ~4x the thread count of v1 and ~1/4 the MUFU
// chain per thread.
// ---------------------------------------------------------------------------
__global__ __launch_bounds__(256) void extract_kernel(
    const float* __restrict__ in,
    const float* __restrict__ anchors)
{
    const int gid = blockIdx.x * 256 + threadIdx.x;
    if (gid >= NP0 * 4) return;
    const int n    = gid >> 2;
    const int part = gid & 3;
    const int a  = n / HW_;
    const int hw = n - a * HW_;

    const float* p = in + (long)(a * 85) * HW_ + hw;   // batch 0

    // chunked class argmax: classes [part*20, part*20+20)
    const int c0 = part * 20;
    float cc = sigf(p[(long)(5 + c0) * HW_]);
    int   cp = c0;
    #pragma unroll
    for (int k = 1; k < 20; k++) {
        float v = sigf(p[(long)(5 + c0 + k) * HW_]);
        if (v > cc) { cc = v; cp = c0 + k; }   // strict > : lowest idx in chunk
    }
    // combine across the 4 parts (4-aligned groups within the warp)
    #pragma unroll
    for (int off = 1; off < 4; off <<= 1) {
        float occ = __shfl_xor_sync(0xffffffffu, cc, off);
        int   ocp = __shfl_xor_sync(0xffffffffu, cp, off);
        if (occ > cc || (occ == cc && ocp < cp)) { cc = occ; cp = ocp; }
    }
    if (part != 0) return;

    float conf = sigf(p[(long)4 * HW_]);
    float score = conf * cc;
    if (score < 0.5f) return;

    const int gy = hw / 52;
    const int gx = hw - gy * 52;
    float aw = anchors[(6 + a) * 2 + 0] * 0.125f;
    float ah = anchors[(6 + a) * 2 + 1] * 0.125f;
    float bx = (sigf(p[0]) + (float)gx) / 52.0f;
    float by = (sigf(p[(long)1 * HW_]) + (float)gy) / 52.0f;
    float bw = (expf(p[(long)2 * HW_]) * aw) / 52.0f;
    float bh = (expf(p[(long)3 * HW_]) * ah) / 52.0f;

    float hx = bw * 0.5f, hy = bh * 0.5f;
    float x1 = bx - hx, y1 = by - hy, x2 = bx + hx, y2 = by + hy;
    float off2 = (float)cp * 4096.0f;
    g_corners[n] = make_float4(x1, y1, x2, y2);
    g_obox[n]    = make_float4(x1 + off2, y1 + off2, x2 + off2, y2 + off2);
    g_conf[n]    = conf;
    g_clsconf[n] = cc;
    g_clspred[n] = (float)cp;
    uint64_t key = ((uint64_t)(__float_as_uint(score) ^ 0xFFFFFFFFu) << 20)
                 | ((uint64_t)(unsigned)n << 7) | (unsigned)cp;
    int pos = atomicAdd(&g_cls_cnt[cp], 1);
    if (pos < CLS_CAP) g_cls_list[cp * CLS_CAP + pos] = key;
}

// ---------------------------------------------------------------------------
// Decode: pure layout transform (unchanged from R12).
// ---------------------------------------------------------------------------
__global__ __launch_bounds__(256) void decode_kernel(
    const float* __restrict__ in,
    const float* __restrict__ anchors,
    float* __restrict__ out)
{
    __shared__ float sm[64 * ATTRS];
    const int tx = threadIdx.x;
    const int q  = tx >> 6;
    const int lp = tx & 63;
    const int n  = blockIdx.x * 64 + lp;
    const int b  = n / NP0;
    const int r  = n - b * NP0;
    const int a  = r / HW_;
    const int hw = r - a * HW_;
    const int gy = hw / 52;
    const int gx = hw - gy * 52;

    const float* p = in + ((long)(b * 255 + a * 85)) * HW_ + hw;
    float* row = sm + lp * ATTRS;

    float t[22];
    #pragma unroll
    for (int k = 0; k < 22; k++) {
        int e = q + 4 * k;
        if (e < ATTRS) t[k] = __ldcs(p + (long)e * HW_);
    }

    if (q == 0) {
        row[0] = (sigf(t[0]) + (float)gx) / 52.0f;
        row[4] = sigf(t[1]);
        #pragma unroll
        for (int k = 2; k < 22; k++) row[4 * k] = sigf(t[k]);
    } else if (q == 1) {
        row[1] = (sigf(t[0]) + (float)gy) / 52.0f;
        #pragma unroll
        for (int k = 1; k < 21; k++) row[1 + 4 * k] = sigf(t[k]);
    } else if (q == 2) {
        float aw = anchors[(6 + a) * 2 + 0] * 0.125f;
        row[2] = (expf(t[0]) * aw) / 52.0f;
        #pragma unroll
        for (int k = 1; k < 21; k++) row[2 + 4 * k] = sigf(t[k]);
    } else {
        float ah = anchors[(6 + a) * 2 + 1] * 0.125f;
        row[3] = (expf(t[0]) * ah) / 52.0f;
        #pragma unroll
        for (int k = 1; k < 21; k++) row[3 + 4 * k] = sigf(t[k]);
    }
    __syncthreads();

    const float4* sm4 = (const float4*)sm;
    float4* ob4 = (float4*)(out + (long)blockIdx.x * (64 * ATTRS));
    #pragma unroll 6
    for (int i = tx; i < (64 * ATTRS) / 4; i += 256) __stcs(ob4 + i, sm4[i]);
}

// ---------------------------------------------------------------------------
// Fused NMS (unchanged from R12)
// ---------------------------------------------------------------------------
__global__ __launch_bounds__(256) void nms_kernel(float* __restrict__ out)
{
    __shared__ __align__(16) char buf[45056];
    uint64_t* s_key  = (uint64_t*)buf;
    uint64_t* s_sort = (uint64_t*)(buf + 8192);
    float4*   s_box  = (float4*)(buf + 16384);
    unsigned* s_thr  = (unsigned*)(buf + 32768);
    int*      s_hist = (int*)buf;
    uint64_t* s_pool = (uint64_t*)(buf + 32768);

    __shared__ int s_kidx[MAXDET];
    __shared__ int s_ord[MAXDET];
    __shared__ int s_nk, s_gbase, s_ticket, s_bstar, s_pcnt;

    const int tid = threadIdx.x;
    const int c   = blockIdx.x;
    int nc = g_cls_cnt[c]; if (nc > CLS_CAP) nc = CLS_CAP;

    for (int i = tid; i < nc; i += 256) s_key[i] = g_cls_list[c * CLS_CAP + i];
    __syncthreads();

    for (int i = tid; i < nc; i += 256) {
        uint64_t my = s_key[i];
        int rk = 0;
        for (int j = 0; j < nc; j++) rk += (s_key[j] < my) ? 1 : 0;
        s_sort[rk] = my;
    }
    __syncthreads();

    for (int i = tid; i < nc; i += 256) {
        int orig = (int)((s_sort[i] >> 7) & 0x1FFFu);
        s_box[i] = g_obox[orig];
    }
    __syncthreads();

    if (nc <= MTX_CAP) {
        if (tid < nc) {
            unsigned w[MTX_W];
            #pragma unroll
            for (int k = 0; k < MTX_W; k++) w[k] = 0u;
            float4 Q = s_box[tid];
            float aI = (Q.z - Q.x) * (Q.w - Q.y);
            for (int j = 0; j < tid; j++) {
                float4 P = s_box[j];
                float aJ = (P.z - P.x) * (P.w - P.y);
                float ltx = fmaxf(P.x, Q.x), lty = fmaxf(P.y, Q.y);
                float rbx = fminf(P.z, Q.z), rby = fminf(P.w, Q.w);
                float iw = fmaxf(rbx - ltx, 0.0f), ih = fmaxf(rby - lty, 0.0f);
                float inter = iw * ih;
                float den = aJ + aI - inter + 1e-9f;
                if (inter / den > 0.4f) w[j >> 5] |= 1u << (j & 31);
            }
            #pragma unroll
            for (int k = 0; k < MTX_W; k++) s_thr[tid * MTX_W + k] = w[k];
        }
        __syncthreads();

        if (tid < 32) {
            unsigned kw = 0u;
            int nk = 0;
            for (int i = 0; i < nc && nk < MAXDET; i++) {
                unsigned tw = (tid < MTX_W) ? (s_thr[i * MTX_W + tid] & kw) : 0u;
                if (__ballot_sync(0xffffffffu, tw != 0u) == 0u) {
                    if (tid == 0) s_kidx[nk] = i;
                    if (tid == (i >> 5)) kw |= 1u << (i & 31);
                    nk++;
                }
            }
            if (tid == 0) s_nk = nk;
        }
    } else {
        if (tid < 32) {
            const int lane = tid;
            int nk = 0;
            for (int i = 0; i < nc && nk < MAXDET; i++) {
                float4 B = s_box[i];
                float aC = (B.z - B.x) * (B.w - B.y);
                bool sup = false;
                #pragma unroll
                for (int t = 0; t < 4; t++) {
                    int idx = lane + (t << 5);
                    if (idx < nk) {
                        float4 K = s_box[s_kidx[idx]];
                        float aK = (K.z - K.x) * (K.w - K.y);
                        float ltx = fmaxf(K.x, B.x), lty = fmaxf(K.y, B.y);
                        float rbx = fminf(K.z, B.z), rby = fminf(K.w, B.w);
                        float iw = fmaxf(rbx - ltx, 0.0f), ih = fmaxf(rby - lty, 0.0f);
                        float inter = iw * ih;
                        float den = aK + aC - inter + 1e-9f;
                        if (inter / den > 0.4f) sup = true;
                    }
                }
                if (__ballot_sync(0xffffffffu, sup) == 0u) {
                    if (lane == 0) s_kidx[nk] = i;
                    nk++;
                    __syncwarp();
                }
            }
            if (lane == 0) s_nk = nk;
        }
    }
    __syncthreads();

    const int nk = s_nk;
    if (tid == 0) s_gbase = (nk > 0) ? atomicAdd(&g_kcount, nk) : 0;
    __syncthreads();
    for (int t = tid; t < nk; t += 256) {
        int gp = s_gbase + t;
        if (gp < KEPT_MAX) g_kept[gp] = s_sort[s_kidx[t]];
    }
    if (tid == 0) g_cls_cnt[c] = 0;

    __syncthreads();
    if (tid == 0) {
        __threadfence();
        s_ticket = atomicAdd(&g_done, 1);
    }
    __syncthreads();
    if (s_ticket != NCLS - 1) return;

    if (tid == 0) __threadfence();
    __syncthreads();

    int K = g_kcount; if (K > KEPT_MAX) K = KEPT_MAX;
    const int np = (K < MAXDET) ? K : MAXDET;

    for (int i = tid; i < NBUCK; i += 256) s_hist[i] = 0;
    if (tid == 0) { s_pcnt = 0; s_bstar = -1; }
    __syncthreads();

    for (int i = tid; i < K; i += 256)
        atomicAdd(&s_hist[(int)((g_kept[i] >> 31) & 0x1FFFu)], 1);
    __syncthreads();

    if (tid < 32 && np > 0) {
        const int CH = NBUCK / 32;
        int sum = 0;
        for (int j = 0; j < CH; j++) sum += s_hist[tid * CH + j];
        int excl = sum;
        #pragma unroll
        for (int off = 1; off < 32; off <<= 1) {
            int v = __shfl_up_sync(0xffffffffu, excl, off);
            if ((int)tid >= off) excl += v;
        }
        excl -= sum;
        bool has = (excl < np) && (excl + sum >= np);
        unsigned bal = __ballot_sync(0xffffffffu, has);
        int src = __ffs(bal) - 1;
        if ((int)tid == src) {
            int run = excl;
            for (int j = 0; j < CH; j++) {
                run += s_hist[tid * CH + j];
                if (run >= np) { s_bstar = tid * CH + j; break; }
            }
        }
    }
    __syncthreads();

    const int bstar = s_bstar;
    for (int i = tid; i < K; i += 256) {
        uint64_t k = g_kept[i];
        if ((int)((k >> 31) & 0x1FFFu) <= bstar) {
            int p = atomicAdd(&s_pcnt, 1);
            if (p < POOL_CAP) s_pool[p] = k;
        }
    }
    __syncthreads();

    int P = s_pcnt; if (P > POOL_CAP) P = POOL_CAP;
    for (int i = tid; i < P; i += 256) {
        uint64_t my = s_pool[i];
        int rk = 0;
        for (int j = 0; j < P; j++) rk += (s_pool[j] < my) ? 1 : 0;
        if (rk < np) s_ord[rk] = (int)((my >> 7) & 0x1FFFu);
    }
    __syncthreads();

    if (tid < MAXDET) {
        float* d = out + (long)OUT_ELEMS + tid * 7;
        if (tid < np) {
            int orig = s_ord[tid];
            float4 c4 = g_corners[orig];
            d[0] = c4.y * 416.0f;
            d[1] = c4.x * 416.0f;
            d[2] = c4.w * 416.0f;
            d[3] = c4.z * 416.0f;
            d[4] = g_conf[orig];
            d[5] = g_clsconf[orig];
            d[6] = g_clspred[orig];
        } else {
            #pragma unroll
            for (int e = 0; e < 7; e++) d[e] = 0.0f;
        }
    }

    if (tid == 0) { g_kcount = 0; g_done = 0; }
}

// ---------------------------------------------------------------------------
// Launch: fork at t=0. Side: extract(b0) -> nms. Main: full decode.
// ---------------------------------------------------------------------------
extern "C" void kernel_launch(void* const* d_in, const int* in_sizes, int n_in,
                              void* d_out, int out_size)
{
    const float* in      = (const float*)d_in[0];
    const float* anchors = (const float*)d_in[1];
    float* out = (float*)d_out;

    static cudaStream_t s2 = nullptr;
    static cudaEvent_t  e1 = nullptr, e2 = nullptr;
    if (!s2) {
        cudaStreamCreateWithFlags(&s2, cudaStreamNonBlocking);
        cudaEventCreateWithFlags(&e1, cudaEventDisableTiming);
        cudaEventCreateWithFlags(&e2, cudaEventDisableTiming);
    }

    cudaEventRecord(e1, 0);
    cudaStreamWaitEvent(s2, e1, 0);

    extract_kernel<<<(NP0 * 4 + 255) / 256, 256, 0, s2>>>(in, anchors);
    nms_kernel<<<NCLS, 256, 0, s2>>>(out);

    decode_kernel<<<TOT_BLOCKS, 256>>>(in, anchors, out);

    cudaEventRecord(e2, s2);
    cudaStreamWaitEvent(0, e2, 0);
}

// round 14
// speedup vs baseline: 1.1982x; 1.1579x over previous
#include <cuda_runtime.h>
#include <math.h>
#include <stdint.h>

#define NPRED_TOTAL 259584      // 32 * 8112
#define NP0         8112        // predictions in batch 0 (3*52*52)
#define HW_         2704        // 52*52
#define ATTRS       85
#define OUT_ELEMS   22064640    // 32*8112*85
#define MAXDET      100
#define NCLS        80
#define CLS_CAP     512
#define MTX_CAP     256
#define MTX_W       8
#define KEPT_MAX    8192
#define NBUCK       4096        // (key>>32)&0xFFF : exp-LSB + 11 mantissa bits
#define POOL_CAP    1024
#define TOT_BLOCKS  (NPRED_TOTAL / 64)
#define EXT_BLOCKS  ((NP0 + 63) / 64)

// ---- device scratch ----
__device__ float4   g_obox[NP0];
__device__ float4   g_corners[NP0];
__device__ float    g_conf[NP0];
__device__ float    g_clsconf[NP0];
__device__ float    g_clspred[NP0];
__device__ uint64_t g_cls_list[NCLS * CLS_CAP];
__device__ int      g_cls_cnt[NCLS];
__device__ uint64_t g_kept[KEPT_MAX];
__device__ int      g_kcount;
__device__ int      g_done;

// key (52 bits) = score_inv(32) << 20 | idx(13) << 7 | cls(7)

__device__ __forceinline__ float sigf(float x) { return 1.0f / (1.0f + expf(-x)); }

// ---------------------------------------------------------------------------
// Extract v3: 64 preds/block, 4 warp-aligned class chunks of 20. Lanes span
// consecutive hw -> every load coalesced. Chunk combine in ascending class
// order via smem (strict > keeps lowest class index: exact argmax ties).
// ---------------------------------------------------------------------------
__global__ __launch_bounds__(256) void extract_kernel(
    const float* __restrict__ in,
    const float* __restrict__ anchors)
{
    __shared__ float scc[4][64];
    __shared__ int   scp[4][64];

    const int tx = threadIdx.x;
    const int q  = tx >> 6;                 // class chunk, uniform per warp-pair
    const int lp = tx & 63;
    const int n  = blockIdx.x * 64 + lp;
    const bool ok = (n < NP0);

    const int a  = ok ? (n / HW_) : 0;
    const int hw = ok ? (n - a * HW_) : 0;
    const float* p = in + (long)(a * 85) * HW_ + hw;   // batch 0

    if (ok) {
        const int c0 = q * 20;
        float t[20];
        #pragma unroll
        for (int k = 0; k < 20; k++) t[k] = p[(long)(5 + c0 + k) * HW_];
        float cc = sigf(t[0]); int cp = c0;
        #pragma unroll
        for (int k = 1; k < 20; k++) {
            float v = sigf(t[k]);
            if (v > cc) { cc = v; cp = c0 + k; }   // strict > : lowest idx in chunk
        }
        scc[q][lp] = cc;
        scp[q][lp] = cp;
    }
    __syncthreads();
    if (tx >= 64 || !ok) return;

    // combine chunks in ascending class order (exact sequential-scan semantics)
    float cc = scc[0][lp]; int cp = scp[0][lp];
    #pragma unroll
    for (int q2 = 1; q2 < 4; q2++) {
        float v = scc[q2][lp];
        if (v > cc) { cc = v; cp = scp[q2][lp]; }
    }

    float conf = sigf(p[(long)4 * HW_]);
    float score = conf * cc;
    if (score < 0.5f) return;

    const int gy = hw / 52;
    const int gx = hw - gy * 52;
    float aw = anchors[(6 + a) * 2 + 0] * 0.125f;
    float ah = anchors[(6 + a) * 2 + 1] * 0.125f;
    float bx = (sigf(p[0]) + (float)gx) / 52.0f;
    float by = (sigf(p[(long)1 * HW_]) + (float)gy) / 52.0f;
    float bw = (expf(p[(long)2 * HW_]) * aw) / 52.0f;
    float bh = (expf(p[(long)3 * HW_]) * ah) / 52.0f;

    float hx = bw * 0.5f, hy = bh * 0.5f;
    float x1 = bx - hx, y1 = by - hy, x2 = bx + hx, y2 = by + hy;
    float off = (float)cp * 4096.0f;
    g_corners[n] = make_float4(x1, y1, x2, y2);
    g_obox[n]    = make_float4(x1 + off, y1 + off, x2 + off, y2 + off);
    g_conf[n]    = conf;
    g_clsconf[n] = cc;
    g_clspred[n] = (float)cp;
    uint64_t key = ((uint64_t)(__float_as_uint(score) ^ 0xFFFFFFFFu) << 20)
                 | ((uint64_t)(unsigned)n << 7) | (unsigned)cp;
    int pos = atomicAdd(&g_cls_cnt[cp], 1);
    if (pos < CLS_CAP) g_cls_list[cp * CLS_CAP + pos] = key;
}

// ---------------------------------------------------------------------------
// Decode: pure layout transform (unchanged).
// ---------------------------------------------------------------------------
__global__ __launch_bounds__(256) void decode_kernel(
    const float* __restrict__ in,
    const float* __restrict__ anchors,
    float* __restrict__ out)
{
    __shared__ float sm[64 * ATTRS];
    const int tx = threadIdx.x;
    const int q  = tx >> 6;
    const int lp = tx & 63;
    const int n  = blockIdx.x * 64 + lp;
    const int b  = n / NP0;
    const int r  = n - b * NP0;
    const int a  = r / HW_;
    const int hw = r - a * HW_;
    const int gy = hw / 52;
    const int gx = hw - gy * 52;

    const float* p = in + ((long)(b * 255 + a * 85)) * HW_ + hw;
    float* row = sm + lp * ATTRS;

    float t[22];
    #pragma unroll
    for (int k = 0; k < 22; k++) {
        int e = q + 4 * k;
        if (e < ATTRS) t[k] = __ldcs(p + (long)e * HW_);
    }

    if (q == 0) {
        row[0] = (sigf(t[0]) + (float)gx) / 52.0f;
        row[4] = sigf(t[1]);
        #pragma unroll
        for (int k = 2; k < 22; k++) row[4 * k] = sigf(t[k]);
    } else if (q == 1) {
        row[1] = (sigf(t[0]) + (float)gy) / 52.0f;
        #pragma unroll
        for (int k = 1; k < 21; k++) row[1 + 4 * k] = sigf(t[k]);
    } else if (q == 2) {
        float aw = anchors[(6 + a) * 2 + 0] * 0.125f;
        row[2] = (expf(t[0]) * aw) / 52.0f;
        #pragma unroll
        for (int k = 1; k < 21; k++) row[2 + 4 * k] = sigf(t[k]);
    } else {
        float ah = anchors[(6 + a) * 2 + 1] * 0.125f;
        row[3] = (expf(t[0]) * ah) / 52.0f;
        #pragma unroll
        for (int k = 1; k < 21; k++) row[3 + 4 * k] = sigf(t[k]);
    }
    __syncthreads();

    const float4* sm4 = (const float4*)sm;
    float4* ob4 = (float4*)(out + (long)blockIdx.x * (64 * ATTRS));
    #pragma unroll 6
    for (int i = tx; i < (64 * ATTRS) / 4; i += 256) __stcs(ob4 + i, sm4[i]);
}

// ---------------------------------------------------------------------------
// Fused NMS: smem union shrunk to 24KB so blocks co-schedule with decode.
// ---------------------------------------------------------------------------
__global__ __launch_bounds__(256) void nms_kernel(float* __restrict__ out)
{
    __shared__ __align__(16) char buf[24576];       // 24KB phase union
    uint64_t* s_key  = (uint64_t*)buf;              // [0,4K)
    uint64_t* s_sort = (uint64_t*)(buf + 4096);     // [4K,8K)
    float4*   s_box  = (float4*)(buf + 8192);       // [8K,16K)
    unsigned* s_thr  = (unsigned*)(buf + 16384);    // [16K,24K): 256 x 8 words
    int*      s_hist = (int*)buf;                   // [0,16K)   (merge)
    uint64_t* s_pool = (uint64_t*)(buf + 16384);    // [16K,24K) (merge)

    __shared__ int s_kidx[MAXDET];
    __shared__ int s_ord[MAXDET];
    __shared__ int s_nk, s_gbase, s_ticket, s_bstar, s_pcnt;

    const int tid = threadIdx.x;
    const int c   = blockIdx.x;
    int nc = g_cls_cnt[c]; if (nc > CLS_CAP) nc = CLS_CAP;

    for (int i = tid; i < nc; i += 256) s_key[i] = g_cls_list[c * CLS_CAP + i];
    __syncthreads();

    for (int i = tid; i < nc; i += 256) {
        uint64_t my = s_key[i];
        int rk = 0;
        for (int j = 0; j < nc; j++) rk += (s_key[j] < my) ? 1 : 0;
        s_sort[rk] = my;
    }
    __syncthreads();

    for (int i = tid; i < nc; i += 256) {
        int orig = (int)((s_sort[i] >> 7) & 0x1FFFu);
        s_box[i] = g_obox[orig];
    }
    __syncthreads();

    if (nc <= MTX_CAP) {
        if (tid < nc) {
            unsigned w[MTX_W];
            #pragma unroll
            for (int k = 0; k < MTX_W; k++) w[k] = 0u;
            float4 Q = s_box[tid];
            float aI = (Q.z - Q.x) * (Q.w - Q.y);
            for (int j = 0; j < tid; j++) {
                float4 P = s_box[j];
                float aJ = (P.z - P.x) * (P.w - P.y);
                float ltx = fmaxf(P.x, Q.x), lty = fmaxf(P.y, Q.y);
                float rbx = fminf(P.z, Q.z), rby = fminf(P.w, Q.w);
                float iw = fmaxf(rbx - ltx, 0.0f), ih = fmaxf(rby - lty, 0.0f);
                float inter = iw * ih;
                float den = aJ + aI - inter + 1e-9f;
                if (inter / den > 0.4f) w[j >> 5] |= 1u << (j & 31);
            }
            #pragma unroll
            for (int k = 0; k < MTX_W; k++) s_thr[tid * MTX_W + k] = w[k];
        }
        __syncthreads();

        if (tid < 32) {
            unsigned kw = 0u;
            int nk = 0;
            for (int i = 0; i < nc && nk < MAXDET; i++) {
                unsigned tw = (tid < MTX_W) ? (s_thr[i * MTX_W + tid] & kw) : 0u;
                if (__ballot_sync(0xffffffffu, tw != 0u) == 0u) {
                    if (tid == 0) s_kidx[nk] = i;
                    if (tid == (i >> 5)) kw |= 1u << (i & 31);
                    nk++;
                }
            }
            if (tid == 0) s_nk = nk;
        }
    } else {
        if (tid < 32) {
            const int lane = tid;
            int nk = 0;
            for (int i = 0; i < nc && nk < MAXDET; i++) {
                float4 B = s_box[i];
                float aC = (B.z - B.x) * (B.w - B.y);
                bool sup = false;
                #pragma unroll
                for (int t = 0; t < 4; t++) {
                    int idx = lane + (t << 5);
                    if (idx < nk) {
                        float4 K = s_box[s_kidx[idx]];
                        float aK = (K.z - K.x) * (K.w - K.y);
                        float ltx = fmaxf(K.x, B.x), lty = fmaxf(K.y, B.y);
                        float rbx = fminf(K.z, B.z), rby = fminf(K.w, B.w);
                        float iw = fmaxf(rbx - ltx, 0.0f), ih = fmaxf(rby - lty, 0.0f);
                        float inter = iw * ih;
                        float den = aK + aC - inter + 1e-9f;
                        if (inter / den > 0.4f) sup = true;
                    }
                }
                if (__ballot_sync(0xffffffffu, sup) == 0u) {
                    if (lane == 0) s_kidx[nk] = i;
                    nk++;
                    __syncwarp();
                }
            }
            if (lane == 0) s_nk = nk;
        }
    }
    __syncthreads();

    const int nk = s_nk;
    if (tid == 0) s_gbase = (nk > 0) ? atomicAdd(&g_kcount, nk) : 0;
    __syncthreads();
    for (int t = tid; t < nk; t += 256) {
        int gp = s_gbase + t;
        if (gp < KEPT_MAX) g_kept[gp] = s_sort[s_kidx[t]];
    }
    if (tid == 0) g_cls_cnt[c] = 0;

    __syncthreads();
    if (tid == 0) {
        __threadfence();
        s_ticket = atomicAdd(&g_done, 1);
    }
    __syncthreads();
    if (s_ticket != NCLS - 1) return;

    if (tid == 0) __threadfence();
    __syncthreads();

    // ===== last block: histogram top-100 merge =====
    int K = g_kcount; if (K > KEPT_MAX) K = KEPT_MAX;
    const int np = (K < MAXDET) ? K : MAXDET;

    for (int i = tid; i < NBUCK; i += 256) s_hist[i] = 0;
    if (tid == 0) { s_pcnt = 0; s_bstar = -1; }
    __syncthreads();

    for (int i = tid; i < K; i += 256)
        atomicAdd(&s_hist[(int)((g_kept[i] >> 32) & 0xFFFu)], 1);
    __syncthreads();

    if (tid < 32 && np > 0) {
        const int CH = NBUCK / 32;
        int sum = 0;
        for (int j = 0; j < CH; j++) sum += s_hist[tid * CH + j];
        int excl = sum;
        #pragma unroll
        for (int off = 1; off < 32; off <<= 1) {
            int v = __shfl_up_sync(0xffffffffu, excl, off);
            if ((int)tid >= off) excl += v;
        }
        excl -= sum;
        bool has = (excl < np) && (excl + sum >= np);
        unsigned bal = __ballot_sync(0xffffffffu, has);
        int src = __ffs(bal) - 1;
        if ((int)tid == src) {
            int run = excl;
            for (int j = 0; j < CH; j++) {
                run += s_hist[tid * CH + j];
                if (run >= np) { s_bstar = tid * CH + j; break; }
            }
        }
    }
    __syncthreads();

    const int bstar = s_bstar;
    for (int i = tid; i < K; i += 256) {
        uint64_t k = g_kept[i];
        if ((int)((k >> 32) & 0xFFFu) <= bstar) {
            int p = atomicAdd(&s_pcnt, 1);
            if (p < POOL_CAP) s_pool[p] = k;
        }
    }
    __syncthreads();

    int P = s_pcnt; if (P > POOL_CAP) P = POOL_CAP;
    for (int i = tid; i < P; i += 256) {
        uint64_t my = s_pool[i];
        int rk = 0;
        for (int j = 0; j < P; j++) rk += (s_pool[j] < my) ? 1 : 0;
        if (rk < np) s_ord[rk] = (int)((my >> 7) & 0x1FFFu);
    }
    __syncthreads();

    if (tid < MAXDET) {
        float* d = out + (long)OUT_ELEMS + tid * 7;
        if (tid < np) {
            int orig = s_ord[tid];
            float4 c4 = g_corners[orig];
            d[0] = c4.y * 416.0f;
            d[1] = c4.x * 416.0f;
            d[2] = c4.w * 416.0f;
            d[3] = c4.z * 416.0f;
            d[4] = g_conf[orig];
            d[5] = g_clsconf[orig];
            d[6] = g_clspred[orig];
        } else {
            #pragma unroll
            for (int e = 0; e < 7; e++) d[e] = 0.0f;
        }
    }

    if (tid == 0) { g_kcount = 0; g_done = 0; }
}

// ---------------------------------------------------------------------------
// Launch: fork at t=0. High-priority side stream: extract -> nms.
// Main stream: full decode.
// ---------------------------------------------------------------------------
extern "C" void kernel_launch(void* const* d_in, const int* in_sizes, int n_in,
                              void* d_out, int out_size)
{
    const float* in      = (const float*)d_in[0];
    const float* anchors = (const float*)d_in[1];
    float* out = (float*)d_out;

    static cudaStream_t s2 = nullptr;
    static cudaEvent_t  e1 = nullptr, e2 = nullptr;
    if (!s2) {
        int lo, hi;
        cudaDeviceGetStreamPriorityRange(&lo, &hi);
        cudaStreamCreateWithPriority(&s2, cudaStreamNonBlocking, hi);
        cudaEventCreateWithFlags(&e1, cudaEventDisableTiming);
        cudaEventCreateWithFlags(&e2, cudaEventDisableTiming);
    }

    cudaEventRecord(e1, 0);
    cudaStreamWaitEvent(s2, e1, 0);

    extract_kernel<<<EXT_BLOCKS, 256, 0, s2>>>(in, anchors);
    nms_kernel<<<NCLS, 256, 0, s2>>>(out);

    decode_kernel<<<TOT_BLOCKS, 256>>>(in, anchors, out);

    cudaEventRecord(e2, s2);
    cudaStreamWaitEvent(0, e2, 0);
}

// round 15
// speedup vs baseline: 1.1989x; 1.0005x over previous
#include <cuda_runtime.h>
#include <math.h>
#include <stdint.h>

#define NPRED_TOTAL 259584      // 32 * 8112
#define NP0         8112        // predictions in batch 0 (3*52*52)
#define HW_         2704        // 52*52
#define ATTRS       85
#define OUT_ELEMS   22064640    // 32*8112*85
#define MAXDET      100
#define NCLS        80
#define CLS_CAP     512
#define MTX_CAP     256
#define MTX_W       8
#define KEPT_MAX    8192
#define NBUCK       4096        // (key>>32)&0xFFF : exp-LSB + 11 mantissa bits
#define POOL_CAP    1024
#define TOT_BLOCKS  (NPRED_TOTAL / 64)
#define EXT_BLOCKS  ((NP0 + 63) / 64)

// candidate record: 32B, written once by extract, read once by nms
struct __align__(16) Rec { float4 box; uint64_t key; uint64_t pad; };

// ---- device scratch ----
__device__ float4   g_corners[NP0];
__device__ float    g_conf[NP0];
__device__ float    g_clsconf[NP0];
__device__ float    g_clspred[NP0];
__device__ Rec      g_cls_rec[NCLS * CLS_CAP];
__device__ int      g_cls_cnt[NCLS];             // zero-init; reset per class block
__device__ uint64_t g_kept[KEPT_MAX];
__device__ int      g_kcount;
__device__ int      g_done;

// key (52 bits) = score_inv(32) << 20 | idx(13) << 7 | cls(7)

__device__ __forceinline__ float sigf(float x) { return 1.0f / (1.0f + expf(-x)); }

// ---------------------------------------------------------------------------
// Extract: 64 preds/block, 4 warp-aligned class chunks (coalesced loads),
// smem chunk-combine in ascending class order (exact argmax tie-break).
// Emits 32B records {obox, key} -> class phase needs no indexed box gather.
// ---------------------------------------------------------------------------
__global__ __launch_bounds__(256) void extract_kernel(
    const float* __restrict__ in,
    const float* __restrict__ anchors)
{
    __shared__ float scc[4][64];
    __shared__ int   scp[4][64];

    const int tx = threadIdx.x;
    const int q  = tx >> 6;
    const int lp = tx & 63;
    const int n  = blockIdx.x * 64 + lp;
    const bool ok = (n < NP0);

    const int a  = ok ? (n / HW_) : 0;
    const int hw = ok ? (n - a * HW_) : 0;
    const float* p = in + (long)(a * 85) * HW_ + hw;   // batch 0

    if (ok) {
        const int c0 = q * 20;
        float t[20];
        #pragma unroll
        for (int k = 0; k < 20; k++) t[k] = p[(long)(5 + c0 + k) * HW_];
        float cc = sigf(t[0]); int cp = c0;
        #pragma unroll
        for (int k = 1; k < 20; k++) {
            float v = sigf(t[k]);
            if (v > cc) { cc = v; cp = c0 + k; }   // strict > : lowest idx in chunk
        }
        scc[q][lp] = cc;
        scp[q][lp] = cp;
    }
    __syncthreads();
    if (tx >= 64 || !ok) return;

    float cc = scc[0][lp]; int cp = scp[0][lp];
    #pragma unroll
    for (int q2 = 1; q2 < 4; q2++) {
        float v = scc[q2][lp];
        if (v > cc) { cc = v; cp = scp[q2][lp]; }
    }

    float conf = sigf(p[(long)4 * HW_]);
    float score = conf * cc;
    if (score < 0.5f) return;

    const int gy = hw / 52;
    const int gx = hw - gy * 52;
    float aw = anchors[(6 + a) * 2 + 0] * 0.125f;
    float ah = anchors[(6 + a) * 2 + 1] * 0.125f;
    float bx = (sigf(p[0]) + (float)gx) / 52.0f;
    float by = (sigf(p[(long)1 * HW_]) + (float)gy) / 52.0f;
    float bw = (expf(p[(long)2 * HW_]) * aw) / 52.0f;
    float bh = (expf(p[(long)3 * HW_]) * ah) / 52.0f;

    float hx = bw * 0.5f, hy = bh * 0.5f;
    float x1 = bx - hx, y1 = by - hy, x2 = bx + hx, y2 = by + hy;
    float off = (float)cp * 4096.0f;
    g_corners[n] = make_float4(x1, y1, x2, y2);
    g_conf[n]    = conf;
    g_clsconf[n] = cc;
    g_clspred[n] = (float)cp;
    uint64_t key = ((uint64_t)(__float_as_uint(score) ^ 0xFFFFFFFFu) << 20)
                 | ((uint64_t)(unsigned)n << 7) | (unsigned)cp;
    int pos = atomicAdd(&g_cls_cnt[cp], 1);
    if (pos < CLS_CAP) {
        Rec* r = &g_cls_rec[cp * CLS_CAP + pos];
        r->box = make_float4(x1 + off, y1 + off, x2 + off, y2 + off);
        r->key = key;
    }
}

// ---------------------------------------------------------------------------
// Decode: pure layout transform (unchanged).
// ---------------------------------------------------------------------------
__global__ __launch_bounds__(256) void decode_kernel(
    const float* __restrict__ in,
    const float* __restrict__ anchors,
    float* __restrict__ out)
{
    __shared__ float sm[64 * ATTRS];
    const int tx = threadIdx.x;
    const int q  = tx >> 6;
    const int lp = tx & 63;
    const int n  = blockIdx.x * 64 + lp;
    const int b  = n / NP0;
    const int r  = n - b * NP0;
    const int a  = r / HW_;
    const int hw = r - a * HW_;
    const int gy = hw / 52;
    const int gx = hw - gy * 52;

    const float* p = in + ((long)(b * 255 + a * 85)) * HW_ + hw;
    float* row = sm + lp * ATTRS;

    float t[22];
    #pragma unroll
    for (int k = 0; k < 22; k++) {
        int e = q + 4 * k;
        if (e < ATTRS) t[k] = __ldcs(p + (long)e * HW_);
    }

    if (q == 0) {
        row[0] = (sigf(t[0]) + (float)gx) / 52.0f;
        row[4] = sigf(t[1]);
        #pragma unroll
        for (int k = 2; k < 22; k++) row[4 * k] = sigf(t[k]);
    } else if (q == 1) {
        row[1] = (sigf(t[0]) + (float)gy) / 52.0f;
        #pragma unroll
        for (int k = 1; k < 21; k++) row[1 + 4 * k] = sigf(t[k]);
    } else if (q == 2) {
        float aw = anchors[(6 + a) * 2 + 0] * 0.125f;
        row[2] = (expf(t[0]) * aw) / 52.0f;
        #pragma unroll
        for (int k = 1; k < 21; k++) row[2 + 4 * k] = sigf(t[k]);
    } else {
        float ah = anchors[(6 + a) * 2 + 1] * 0.125f;
        row[3] = (expf(t[0]) * ah) / 52.0f;
        #pragma unroll
        for (int k = 1; k < 21; k++) row[3 + 4 * k] = sigf(t[k]);
    }
    __syncthreads();

    const float4* sm4 = (const float4*)sm;
    float4* ob4 = (float4*)(out + (long)blockIdx.x * (64 * ATTRS));
    #pragma unroll 6
    for (int i = tx; i < (64 * ATTRS) / 4; i += 256) __stcs(ob4 + i, sm4[i]);
}

// ---------------------------------------------------------------------------
// Fused NMS: one 32B-record read hop per class block (no indexed box gather);
// rank-scatter through registers; 24KB smem union; last-block merge.
// ---------------------------------------------------------------------------
__global__ __launch_bounds__(256) void nms_kernel(float* __restrict__ out)
{
    __shared__ __align__(16) char buf[24576];       // 24KB phase union
    uint64_t* s_key  = (uint64_t*)buf;              // [0,4K)  unsorted keys
    uint64_t* s_sort = (uint64_t*)(buf + 4096);     // [4K,8K) sorted keys
    float4*   s_box  = (float4*)(buf + 8192);       // [8K,16K) sorted boxes
    unsigned* s_thr  = (unsigned*)(buf + 16384);    // [16K,24K) threat matrix
    int*      s_hist = (int*)buf;                   // [0,16K)  (merge)
    uint64_t* s_pool = (uint64_t*)(buf + 16384);    // [16K,24K) (merge)

    __shared__ int s_kidx[MAXDET];
    __shared__ int s_ord[MAXDET];
    __shared__ int s_nk, s_gbase, s_ticket, s_bstar, s_pcnt;

    const int tid = threadIdx.x;
    const int c   = blockIdx.x;
    int nc = g_cls_cnt[c]; if (nc > CLS_CAP) nc = CLS_CAP;

    // load records: thread owns slots tid and tid+256 (reg-resident)
    float4 rb0 = make_float4(0,0,0,0), rb1 = make_float4(0,0,0,0);
    uint64_t rk0 = 0, rk1 = 0;
    if (tid < nc)       { Rec r = g_cls_rec[c * CLS_CAP + tid];       rb0 = r.box; rk0 = r.key; s_key[tid] = rk0; }
    if (tid + 256 < nc) { Rec r = g_cls_rec[c * CLS_CAP + tid + 256]; rb1 = r.box; rk1 = r.key; s_key[tid + 256] = rk1; }
    __syncthreads();

    // rank-scatter keys AND boxes (no global gather needed)
    if (tid < nc) {
        int rk = 0;
        for (int j = 0; j < nc; j++) rk += (s_key[j] < rk0) ? 1 : 0;
        s_sort[rk] = rk0; s_box[rk] = rb0;
    }
    if (tid + 256 < nc) {
        int rk = 0;
        for (int j = 0; j < nc; j++) rk += (s_key[j] < rk1) ? 1 : 0;
        s_sort[rk] = rk1; s_box[rk] = rb1;
    }
    __syncthreads();

    if (nc <= MTX_CAP) {
        if (tid < nc) {
            unsigned w[MTX_W];
            #pragma unroll
            for (int k = 0; k < MTX_W; k++) w[k] = 0u;
            float4 Q = s_box[tid];
            float aI = (Q.z - Q.x) * (Q.w - Q.y);
            for (int j = 0; j < tid; j++) {
                float4 P = s_box[j];
                float aJ = (P.z - P.x) * (P.w - P.y);
                float ltx = fmaxf(P.x, Q.x), lty = fmaxf(P.y, Q.y);
                float rbx = fminf(P.z, Q.z), rby = fminf(P.w, Q.w);
                float iw = fmaxf(rbx - ltx, 0.0f), ih = fmaxf(rby - lty, 0.0f);
                float inter = iw * ih;
                float den = aJ + aI - inter + 1e-9f;
                if (inter / den > 0.4f) w[j >> 5] |= 1u << (j & 31);
            }
            #pragma unroll
            for (int k = 0; k < MTX_W; k++) s_thr[tid * MTX_W + k] = w[k];
        }
        __syncthreads();

        if (tid < 32) {
            unsigned kw = 0u;
            int nk = 0;
            for (int i = 0; i < nc && nk < MAXDET; i++) {
                unsigned tw = (tid < MTX_W) ? (s_thr[i * MTX_W + tid] & kw) : 0u;
                if (__ballot_sync(0xffffffffu, tw != 0u) == 0u) {
                    if (tid == 0) s_kidx[nk] = i;
                    if (tid == (i >> 5)) kw |= 1u << (i & 31);
                    nk++;
                }
            }
            if (tid == 0) s_nk = nk;
        }
    } else {
        if (tid < 32) {
            const int lane = tid;
            int nk = 0;
            for (int i = 0; i < nc && nk < MAXDET; i++) {
                float4 B = s_box[i];
                float aC = (B.z - B.x) * (B.w - B.y);
                bool sup = false;
                #pragma unroll
                for (int t = 0; t < 4; t++) {
                    int idx = lane + (t << 5);
                    if (idx < nk) {
                        float4 K = s_box[s_kidx[idx]];
                        float aK = (K.z - K.x) * (K.w - K.y);
                        float ltx = fmaxf(K.x, B.x), lty = fmaxf(K.y, B.y);
                        float rbx = fminf(K.z, B.z), rby = fminf(K.w, B.w);
                        float iw = fmaxf(rbx - ltx, 0.0f), ih = fmaxf(rby - lty, 0.0f);
                        float inter = iw * ih;
                        float den = aK + aC - inter + 1e-9f;
                        if (inter / den > 0.4f) sup = true;
                    }
                }
                if (__ballot_sync(0xffffffffu, sup) == 0u) {
                    if (lane == 0) s_kidx[nk] = i;
                    nk++;
                    __syncwarp();
                }
            }
            if (lane == 0) s_nk = nk;
        }
    }
    __syncthreads();

    const int nk = s_nk;
    if (tid == 0) s_gbase = (nk > 0) ? atomicAdd(&g_kcount, nk) : 0;
    __syncthreads();
    for (int t = tid; t < nk; t += 256) {
        int gp = s_gbase + t;
        if (gp < KEPT_MAX) g_kept[gp] = s_sort[s_kidx[t]];
    }
    if (tid == 0) g_cls_cnt[c] = 0;

    __syncthreads();
    if (tid == 0) {
        __threadfence();
        s_ticket = atomicAdd(&g_done, 1);
    }
    __syncthreads();
    if (s_ticket != NCLS - 1) return;

    if (tid == 0) __threadfence();
    __syncthreads();

    // ===== last block: histogram top-100 merge =====
    int K = g_kcount; if (K > KEPT_MAX) K = KEPT_MAX;
    const int np = (K < MAXDET) ? K : MAXDET;

    for (int i = tid; i < NBUCK; i += 256) s_hist[i] = 0;
    if (tid == 0) { s_pcnt = 0; s_bstar = -1; }
    __syncthreads();

    for (int i = tid; i < K; i += 256)
        atomicAdd(&s_hist[(int)((g_kept[i] >> 32) & 0xFFFu)], 1);
    __syncthreads();

    if (tid < 32 && np > 0) {
        const int CH = NBUCK / 32;
        int sum = 0;
        for (int j = 0; j < CH; j++) sum += s_hist[tid * CH + j];
        int excl = sum;
        #pragma unroll
        for (int off = 1; off < 32; off <<= 1) {
            int v = __shfl_up_sync(0xffffffffu, excl, off);
            if ((int)tid >= off) excl += v;
        }
        excl -= sum;
        bool has = (excl < np) && (excl + sum >= np);
        unsigned bal = __ballot_sync(0xffffffffu, has);
        int src = __ffs(bal) - 1;
        if ((int)tid == src) {
            int run = excl;
            for (int j = 0; j < CH; j++) {
                run += s_hist[tid * CH + j];
                if (run >= np) { s_bstar = tid * CH + j; break; }
            }
        }
    }
    __syncthreads();

    const int bstar = s_bstar;
    for (int i = tid; i < K; i += 256) {
        uint64_t k = g_kept[i];
        if ((int)((k >> 32) & 0xFFFu) <= bstar) {
            int p = atomicAdd(&s_pcnt, 1);
            if (p < POOL_CAP) s_pool[p] = k;
        }
    }
    __syncthreads();

    int P = s_pcnt; if (P > POOL_CAP) P = POOL_CAP;
    for (int i = tid; i < P; i += 256) {
        uint64_t my = s_pool[i];
        int rk = 0;
        for (int j = 0; j < P; j++) rk += (s_pool[j] < my) ? 1 : 0;
        if (rk < np) s_ord[rk] = (int)((my >> 7) & 0x1FFFu);
    }
    __syncthreads();

    if (tid < MAXDET) {
        float* d = out + (long)OUT_ELEMS + tid * 7;
        if (tid < np) {
            int orig = s_ord[tid];
            float4 c4 = g_corners[orig];
            d[0] = c4.y * 416.0f;
            d[1] = c4.x * 416.0f;
            d[2] = c4.w * 416.0f;
            d[3] = c4.z * 416.0f;
            d[4] = g_conf[orig];
            d[5] = g_clsconf[orig];
            d[6] = g_clspred[orig];
        } else {
            #pragma unroll
            for (int e = 0; e < 7; e++) d[e] = 0.0f;
        }
    }

    if (tid == 0) { g_kcount = 0; g_done = 0; }
}

// ---------------------------------------------------------------------------
// Launch: fork at t=0. High-priority side stream: extract -> nms.
// Main stream: full decode.
// ---------------------------------------------------------------------------
extern "C" void kernel_launch(void* const* d_in, const int* in_sizes, int n_in,
                              void* d_out, int out_size)
{
    const float* in      = (const float*)d_in[0];
    const float* anchors = (const float*)d_in[1];
    float* out = (float*)d_out;

    static cudaStream_t s2 = nullptr;
    static cudaEvent_t  e1 = nullptr, e2 = nullptr;
    if (!s2) {
        int lo, hi;
        cudaDeviceGetStreamPriorityRange(&lo, &hi);
        cudaStreamCreateWithPriority(&s2, cudaStreamNonBlocking, hi);
        cudaEventCreateWithFlags(&e1, cudaEventDisableTiming);
        cudaEventCreateWithFlags(&e2, cudaEventDisableTiming);
    }

    cudaEventRecord(e1, 0);
    cudaStreamWaitEvent(s2, e1, 0);

    extract_kernel<<<EXT_BLOCKS, 256, 0, s2>>>(in, anchors);
    nms_kernel<<<NCLS, 256, 0, s2>>>(out);

    decode_kernel<<<TOT_BLOCKS, 256>>>(in, anchors, out);

    cudaEventRecord(e2, s2);
    cudaStreamWaitEvent(0, e2, 0);
}